// round 1
// baseline (speedup 1.0000x reference)
#include <cuda_runtime.h>

// ---------------- static device scratch (no allocation allowed) ----------------
#define MAXN 100000
__device__ float g_h0[MAXN * 64];     // x + agg
__device__ float g_h1[MAXN * 128];    // relu(h0 @ W1 + b1)
__device__ float g_W2f[128 * 128];    // BN1-folded W2
__device__ float g_b2f[128];          // BN1-folded b2
__device__ float g_sum1[128], g_ss1[128];
__device__ float g_sum2[128], g_ss2[128];
__device__ float g_a2[128], g_c2[128];
__device__ int   g_is64;

#define BN_EPS 1e-5f

// ---------------- zero per-launch stats ----------------
__global__ void k_zero_stats() {
    int j = threadIdx.x;
    if (j < 128) {
        g_sum1[j] = 0.f; g_ss1[j] = 0.f;
        g_sum2[j] = 0.f; g_ss2[j] = 0.f;
    }
}

// ---------------- detect int64 vs int32 edge_index ----------------
// If int64 (little-endian, values < 1e5), every odd int32 word is 0.
__global__ void k_detect(const int* __restrict__ idx, int n_pairs) {
    __shared__ int nz;
    if (threadIdx.x == 0) nz = 0;
    __syncthreads();
    int lim = n_pairs < 1024 ? n_pairs : 1024;
    for (int i = threadIdx.x; i < lim; i += blockDim.x)
        if (idx[2 * i + 1] != 0) nz = 1;   // benign race
    __syncthreads();
    if (threadIdx.x == 0) g_is64 = (nz == 0) ? 1 : 0;
}

// ---------------- h0 = x (copy) ----------------
__global__ void k_copy(const float4* __restrict__ x, int n4) {
    float4* d = (float4*)g_h0;
    int stride = gridDim.x * blockDim.x;
    for (int i = blockIdx.x * blockDim.x + threadIdx.x; i < n4; i += stride)
        d[i] = x[i];
}

// ---------------- edge scatter: h0[dst] += x[src]  (vector RED, L2-resident) ----------------
__global__ void k_scatter(const void* __restrict__ eptr, const float* __restrict__ x, int E) {
    const int is64 = g_is64;
    const long long total = (long long)E * 16;   // 16 float4-chunks per edge
    const long long stride = (long long)gridDim.x * blockDim.x;
    for (long long i = (long long)blockIdx.x * blockDim.x + threadIdx.x; i < total; i += stride) {
        int e = (int)(i >> 4);
        int c = (int)(i & 15);
        int src, dst;
        if (is64) {
            const long long* p = (const long long*)eptr;
            src = (int)p[e];
            dst = (int)p[E + e];
        } else {
            const int* p = (const int*)eptr;
            src = p[e];
            dst = p[E + e];
        }
        float4 v = __ldg((const float4*)x + (long long)src * 16 + c);
        float* d = g_h0 + (long long)dst * 64 + c * 4;
        asm volatile("red.global.add.v4.f32 [%0], {%1,%2,%3,%4};"
                     :: "l"(d), "f"(v.x), "f"(v.y), "f"(v.z), "f"(v.w) : "memory");
    }
}

// ---------------- fused GEMM (X[N,K] @ W[K,128] + B) -> relu -> Y[N,128] ----------------
// Block: 256 threads, 64-row tile, thread = (row r = tid&63, colgroup cg = tid>>6, 32 cols).
// sx padded to stride K+1 => bank = (r + k) % 32 conflict-free; sw reads are warp-broadcast.
template <int K>
__global__ void k_gemm_relu(const float* __restrict__ X, const float* __restrict__ W,
                            const float* __restrict__ B, float* __restrict__ Y, int N) {
    extern __shared__ float smem[];
    constexpr int XS = K + 1;
    float* sx = smem;               // 64 * XS
    float* sw = smem + 64 * XS;     // K * 128
    const int tid  = threadIdx.x;
    const int row0 = blockIdx.x * 64;

    // stage W (K*128 floats = K*32 float4)
    for (int f = tid; f < K * 32; f += 256)
        ((float4*)sw)[f] = __ldg((const float4*)W + f);

    // stage X tile (64 rows x K), padded stride XS
    for (int f = tid; f < 64 * (K / 4); f += 256) {
        int r  = f / (K / 4);
        int c4 = f % (K / 4);
        int row = row0 + r;
        float4 v = (row < N) ? __ldg((const float4*)(X + (long long)row * K) + c4)
                             : make_float4(0.f, 0.f, 0.f, 0.f);
        float* d = sx + r * XS + c4 * 4;
        d[0] = v.x; d[1] = v.y; d[2] = v.z; d[3] = v.w;
    }
    __syncthreads();

    const int r  = tid & 63;
    const int cg = tid >> 6;
    const float* xr = sx + r * XS;

    float acc[32];
#pragma unroll
    for (int j = 0; j < 32; j++) acc[j] = 0.f;

#pragma unroll 4
    for (int k = 0; k < K; k++) {
        float xv = xr[k];
        const float4* wr = (const float4*)(sw + k * 128) + cg * 8;
#pragma unroll
        for (int j4 = 0; j4 < 8; j4++) {
            float4 w = wr[j4];
            acc[4 * j4 + 0] = fmaf(xv, w.x, acc[4 * j4 + 0]);
            acc[4 * j4 + 1] = fmaf(xv, w.y, acc[4 * j4 + 1]);
            acc[4 * j4 + 2] = fmaf(xv, w.z, acc[4 * j4 + 2]);
            acc[4 * j4 + 3] = fmaf(xv, w.w, acc[4 * j4 + 3]);
        }
    }

    int row = row0 + r;
    if (row < N) {
        float* yr = Y + (long long)row * 128 + cg * 32;
#pragma unroll
        for (int j4 = 0; j4 < 8; j4++) {
            float4 o;
            o.x = fmaxf(acc[4 * j4 + 0] + __ldg(B + cg * 32 + 4 * j4 + 0), 0.f);
            o.y = fmaxf(acc[4 * j4 + 1] + __ldg(B + cg * 32 + 4 * j4 + 1), 0.f);
            o.z = fmaxf(acc[4 * j4 + 2] + __ldg(B + cg * 32 + 4 * j4 + 2), 0.f);
            o.w = fmaxf(acc[4 * j4 + 3] + __ldg(B + cg * 32 + 4 * j4 + 3), 0.f);
            ((float4*)yr)[j4] = o;
        }
    }
}

// ---------------- per-feature sum / sumsq over rows (128 cols) ----------------
__global__ void k_stats(const float* __restrict__ H, int N, float* __restrict__ sum,
                        float* __restrict__ ss) {
    const int lane   = threadIdx.x & 31;
    const int warp   = (blockIdx.x * blockDim.x + threadIdx.x) >> 5;
    const int nwarps = (gridDim.x * blockDim.x) >> 5;
    float4 s = make_float4(0, 0, 0, 0), q = make_float4(0, 0, 0, 0);
    for (int r = warp; r < N; r += nwarps) {
        float4 v = __ldg((const float4*)(H + (long long)r * 128) + lane);
        s.x += v.x; s.y += v.y; s.z += v.z; s.w += v.w;
        q.x = fmaf(v.x, v.x, q.x); q.y = fmaf(v.y, v.y, q.y);
        q.z = fmaf(v.z, v.z, q.z); q.w = fmaf(v.w, v.w, q.w);
    }
    int col = lane * 4;
    atomicAdd(&sum[col + 0], s.x); atomicAdd(&sum[col + 1], s.y);
    atomicAdd(&sum[col + 2], s.z); atomicAdd(&sum[col + 3], s.w);
    atomicAdd(&ss[col + 0], q.x);  atomicAdd(&ss[col + 1], q.y);
    atomicAdd(&ss[col + 2], q.z);  atomicAdd(&ss[col + 3], q.w);
}

// ---------------- fold BN1 into W2/b2: W2f = diag(a1) W2, b2f = b2 + c1^T W2 ----------------
__global__ void k_fold1(const float* __restrict__ W2, const float* __restrict__ b2,
                        const float* __restrict__ g1, const float* __restrict__ be1,
                        float invN) {
    __shared__ float a_s[128], c_s[128];
    int j = threadIdx.x;
    float mean = g_sum1[j] * invN;
    float var  = g_ss1[j] * invN - mean * mean;
    float a    = g1[j] * rsqrtf(var + BN_EPS);
    a_s[j] = a;
    c_s[j] = be1[j] - a * mean;
    __syncthreads();
    float acc = 0.f;
    for (int k = 0; k < 128; k++) {
        float w = W2[k * 128 + j];
        g_W2f[k * 128 + j] = a_s[k] * w;
        acc = fmaf(c_s[k], w, acc);
    }
    g_b2f[j] = b2[j] + acc;
}

// ---------------- BN2 coefficients ----------------
__global__ void k_a2c2(const float* __restrict__ g2, const float* __restrict__ be2, float invN) {
    int j = threadIdx.x;
    float mean = g_sum2[j] * invN;
    float var  = g_ss2[j] * invN - mean * mean;
    float a    = g2[j] * rsqrtf(var + BN_EPS);
    g_a2[j] = a;
    g_c2[j] = be2[j] - a * mean;
}

// ---------------- BN2 apply in place on d_out ----------------
__global__ void k_bn2(float4* __restrict__ Y, int n4) {
    int stride = gridDim.x * blockDim.x;
    for (int i = blockIdx.x * blockDim.x + threadIdx.x; i < n4; i += stride) {
        int c4 = i & 31;
        float4 v = Y[i];
        float4 a = __ldg((const float4*)g_a2 + c4);
        float4 c = __ldg((const float4*)g_c2 + c4);
        v.x = fmaf(a.x, v.x, c.x);
        v.y = fmaf(a.y, v.y, c.y);
        v.z = fmaf(a.z, v.z, c.z);
        v.w = fmaf(a.w, v.w, c.w);
        Y[i] = v;
    }
}

// ---------------- launcher ----------------
extern "C" void kernel_launch(void* const* d_in, const int* in_sizes, int n_in,
                              void* d_out, int out_size) {
    const float* x   = (const float*)d_in[0];
    const void*  eix = d_in[1];
    const float* W1  = (const float*)d_in[2];
    const float* b1  = (const float*)d_in[3];
    const float* g1  = (const float*)d_in[4];
    const float* be1 = (const float*)d_in[5];
    const float* W2  = (const float*)d_in[6];
    const float* b2  = (const float*)d_in[7];
    const float* g2  = (const float*)d_in[8];
    const float* be2 = (const float*)d_in[9];
    float* out = (float*)d_out;

    const int N = in_sizes[0] / 64;
    const int E = in_sizes[1] / 2;

    const int SMEM1 = (64 * 65 + 64 * 128) * 4;    // 49 408 B
    const int SMEM2 = (64 * 129 + 128 * 128) * 4;  // 98 560 B
    cudaFuncSetAttribute(k_gemm_relu<64>, cudaFuncAttributeMaxDynamicSharedMemorySize, SMEM1);
    cudaFuncSetAttribute(k_gemm_relu<128>, cudaFuncAttributeMaxDynamicSharedMemorySize, SMEM2);

    // resolve device-symbol addresses (host API, capture-safe, no allocation)
    void *p_h0, *p_h1, *p_W2f, *p_b2f, *p_s1, *p_q1, *p_s2, *p_q2;
    cudaGetSymbolAddress(&p_h0, g_h0);
    cudaGetSymbolAddress(&p_h1, g_h1);
    cudaGetSymbolAddress(&p_W2f, g_W2f);
    cudaGetSymbolAddress(&p_b2f, g_b2f);
    cudaGetSymbolAddress(&p_s1, g_sum1);
    cudaGetSymbolAddress(&p_q1, g_ss1);
    cudaGetSymbolAddress(&p_s2, g_sum2);
    cudaGetSymbolAddress(&p_q2, g_ss2);

    const int GB = 148 * 8;      // grid for grid-stride kernels
    const int gb_gemm = (N + 63) / 64;
    const float invN = 1.0f / (float)N;

    k_zero_stats<<<1, 128>>>();
    k_detect<<<1, 256>>>((const int*)eix, E);
    k_copy<<<GB, 256>>>((const float4*)x, N * 16);
    k_scatter<<<GB * 2, 256>>>(eix, x, E);
    k_gemm_relu<64><<<gb_gemm, 256, SMEM1>>>((const float*)p_h0, W1, b1, (float*)p_h1, N);
    k_stats<<<GB, 256>>>((const float*)p_h1, N, (float*)p_s1, (float*)p_q1);
    k_fold1<<<1, 128>>>(W2, b2, g1, be1, invN);
    k_gemm_relu<128><<<gb_gemm, 256, SMEM2>>>((const float*)p_h1, (const float*)p_W2f,
                                              (const float*)p_b2f, out, N);
    k_stats<<<GB, 256>>>(out, N, (float*)p_s2, (float*)p_q2);
    k_a2c2<<<1, 128>>>(g2, be2, invN);
    k_bn2<<<GB, 256>>>((float4*)out, N * 32);
}

// round 2
// speedup vs baseline: 2.5178x; 2.5178x over previous
#include <cuda_runtime.h>

// ---------------- static device scratch (no allocation allowed) ----------------
#define MAXN 100000
__device__ float g_h0[MAXN * 64];     // x + agg
__device__ float g_h1[MAXN * 128];    // relu(h0 @ W1 + b1)  (BN1 folded into W2)
__device__ float g_W2f[128 * 128];    // BN1-folded W2
__device__ float g_b2f[128];          // BN1-folded b2
__device__ float g_sum1[128], g_ss1[128];
__device__ float g_sum2[128], g_ss2[128];
__device__ float g_a2[128], g_c2[128];
__device__ int   g_is64;

#define BN_EPS 1e-5f

// packed f32x2 FMA (sm_103a; ptxas never emits this from C++ -- PTX only)
#define FMA2(d, a, b, c) \
    asm("fma.rn.f32x2 %0, %1, %2, %3;" : "=l"(d) : "l"(a), "l"(b), "l"(c))
#define DUP_F32X2(d, f) \
    asm("mov.b64 %0, {%1, %1};" : "=l"(d) : "f"(f))
#define UNPACK_F32X2(lo, hi, p) \
    asm("mov.b64 {%0, %1}, %2;" : "=f"(lo), "=f"(hi) : "l"(p))

// ---------------- zero per-launch stats ----------------
__global__ void k_zero_stats() {
    int j = threadIdx.x;
    if (j < 128) {
        g_sum1[j] = 0.f; g_ss1[j] = 0.f;
        g_sum2[j] = 0.f; g_ss2[j] = 0.f;
    }
}

// ---------------- detect int64 vs int32 edge_index ----------------
__global__ void k_detect(const int* __restrict__ idx, int n_pairs) {
    __shared__ int nz;
    if (threadIdx.x == 0) nz = 0;
    __syncthreads();
    int lim = n_pairs < 1024 ? n_pairs : 1024;
    for (int i = threadIdx.x; i < lim; i += blockDim.x)
        if (idx[2 * i + 1] != 0) nz = 1;   // benign race
    __syncthreads();
    if (threadIdx.x == 0) g_is64 = (nz == 0) ? 1 : 0;
}

// ---------------- h0 = x (copy) ----------------
__global__ void k_copy(const float4* __restrict__ x, int n4) {
    float4* d = (float4*)g_h0;
    int stride = gridDim.x * blockDim.x;
    for (int i = blockIdx.x * blockDim.x + threadIdx.x; i < n4; i += stride)
        d[i] = x[i];
}

// ---------------- edge scatter: h0[dst] += x[src]  (vector RED, L2-resident) ----------------
__global__ void k_scatter(const void* __restrict__ eptr, const float* __restrict__ x, int E) {
    const int is64 = g_is64;
    const long long total = (long long)E * 16;   // 16 float4-chunks per edge
    const long long stride = (long long)gridDim.x * blockDim.x;
    for (long long i = (long long)blockIdx.x * blockDim.x + threadIdx.x; i < total; i += stride) {
        int e = (int)(i >> 4);
        int c = (int)(i & 15);
        int src, dst;
        if (is64) {
            const long long* p = (const long long*)eptr;
            src = (int)p[e];
            dst = (int)p[E + e];
        } else {
            const int* p = (const int*)eptr;
            src = p[e];
            dst = p[E + e];
        }
        float4 v = __ldg((const float4*)x + (long long)src * 16 + c);
        float* d = g_h0 + (long long)dst * 64 + c * 4;
        asm volatile("red.global.add.v4.f32 [%0], {%1,%2,%3,%4};"
                     :: "l"(d), "f"(v.x), "f"(v.y), "f"(v.z), "f"(v.w) : "memory");
    }
}

// ---------------- register-tiled GEMM + relu + fused BN stats ----------------
// Block 256 threads, tile 128 rows x 128 cols. Thread (tx=tid&15, ty=tid>>4)
// computes rows ty*8..+7, cols tx*8..+7 (8x8), accumulating in f32x2 pairs.
// W[k][0..127] and X tile both SMEM-resident. Inner loop: 2 LDS.128 (W pairs
// read directly as b64) + 8 LDS.32 (x broadcast) + 8 dup + 32 FFMA2.
template <int K>
__global__ void __launch_bounds__(256, 1)
k_gemm_relu_stats(const float* __restrict__ X, const float* __restrict__ W,
                  const float* __restrict__ B, float* __restrict__ Y, int N,
                  float* __restrict__ gsum, float* __restrict__ gss) {
    extern __shared__ float smem[];
    float* sx = smem;               // 128 * K
    float* sw = smem + 128 * K;     // K * 128
    __shared__ float ssum[128], sss[128];

    const int tid  = threadIdx.x;
    const int row0 = blockIdx.x * 128;

    // stage W (K*128 floats)
    for (int f = tid; f < K * 32; f += 256)
        ((float4*)sw)[f] = __ldg((const float4*)W + f);

    // stage X tile (128 rows x K floats), zero-pad OOB rows
    for (int f = tid; f < 128 * (K / 4); f += 256) {
        int r  = f / (K / 4);
        int c4 = f % (K / 4);
        int row = row0 + r;
        float4 v = (row < N) ? __ldg((const float4*)(X + (long long)row * K) + c4)
                             : make_float4(0.f, 0.f, 0.f, 0.f);
        ((float4*)(sx + r * K))[c4] = v;
    }
    if (tid < 128) { ssum[tid] = 0.f; sss[tid] = 0.f; }
    __syncthreads();

    const int tx = tid & 15;    // cols tx*8 .. tx*8+7
    const int ty = tid >> 4;    // rows ty*8 .. ty*8+7
    const float* xb = sx + ty * 8 * K;
    const float* wb = sw + tx * 8;

    unsigned long long acc[8][4];
#pragma unroll
    for (int i = 0; i < 8; i++)
#pragma unroll
        for (int j = 0; j < 4; j++) acc[i][j] = 0ULL;

#pragma unroll 2
    for (int k = 0; k < K; k++) {
        // 4 column-pairs of W for this thread's 8 columns
        ulonglong2 wa = *(const ulonglong2*)(wb + (long long)k * 128);
        ulonglong2 wc = *(const ulonglong2*)(wb + (long long)k * 128 + 4);
#pragma unroll
        for (int i = 0; i < 8; i++) {
            float xv = xb[i * K + k];
            unsigned long long xp;
            DUP_F32X2(xp, xv);
            FMA2(acc[i][0], xp, wa.x, acc[i][0]);
            FMA2(acc[i][1], xp, wa.y, acc[i][1]);
            FMA2(acc[i][2], xp, wc.x, acc[i][2]);
            FMA2(acc[i][3], xp, wc.y, acc[i][3]);
        }
    }

    // bias for my 8 cols
    float bias[8];
#pragma unroll
    for (int j = 0; j < 8; j++) bias[j] = __ldg(B + tx * 8 + j);

    float csum[8], csq[8];
#pragma unroll
    for (int j = 0; j < 8; j++) { csum[j] = 0.f; csq[j] = 0.f; }

#pragma unroll
    for (int i = 0; i < 8; i++) {
        int row = row0 + ty * 8 + i;
        if (row < N) {
            float o[8];
#pragma unroll
            for (int j = 0; j < 4; j++)
                UNPACK_F32X2(o[2 * j], o[2 * j + 1], acc[i][j]);
#pragma unroll
            for (int j = 0; j < 8; j++) {
                o[j] = fmaxf(o[j] + bias[j], 0.f);
                csum[j] += o[j];
                csq[j]  = fmaf(o[j], o[j], csq[j]);
            }
            float* yr = Y + (long long)row * 128 + tx * 8;
            ((float4*)yr)[0] = make_float4(o[0], o[1], o[2], o[3]);
            ((float4*)yr)[1] = make_float4(o[4], o[5], o[6], o[7]);
        }
    }

    // block-level stats reduction, then one global atomic per feature
#pragma unroll
    for (int j = 0; j < 8; j++) {
        atomicAdd(&ssum[tx * 8 + j], csum[j]);
        atomicAdd(&sss[tx * 8 + j], csq[j]);
    }
    __syncthreads();
    if (tid < 128) {
        atomicAdd(&gsum[tid], ssum[tid]);
        atomicAdd(&gss[tid], sss[tid]);
    }
}

// ---------------- fold BN1 into W2/b2: W2f = diag(a1) W2, b2f = b2 + c1^T W2 ----------------
__global__ void k_fold1(const float* __restrict__ W2, const float* __restrict__ b2,
                        const float* __restrict__ g1, const float* __restrict__ be1,
                        float invN) {
    __shared__ float a_s[128], c_s[128];
    int j = threadIdx.x;
    float mean = g_sum1[j] * invN;
    float var  = g_ss1[j] * invN - mean * mean;
    float a    = g1[j] * rsqrtf(var + BN_EPS);
    a_s[j] = a;
    c_s[j] = be1[j] - a * mean;
    __syncthreads();
    float acc = 0.f;
    for (int k = 0; k < 128; k++) {
        float w = W2[k * 128 + j];
        g_W2f[k * 128 + j] = a_s[k] * w;
        acc = fmaf(c_s[k], w, acc);
    }
    g_b2f[j] = b2[j] + acc;
}

// ---------------- BN2 coefficients ----------------
__global__ void k_a2c2(const float* __restrict__ g2, const float* __restrict__ be2, float invN) {
    int j = threadIdx.x;
    float mean = g_sum2[j] * invN;
    float var  = g_ss2[j] * invN - mean * mean;
    float a    = g2[j] * rsqrtf(var + BN_EPS);
    g_a2[j] = a;
    g_c2[j] = be2[j] - a * mean;
}

// ---------------- BN2 apply in place on d_out ----------------
__global__ void k_bn2(float4* __restrict__ Y, int n4) {
    int stride = gridDim.x * blockDim.x;
    for (int i = blockIdx.x * blockDim.x + threadIdx.x; i < n4; i += stride) {
        int c4 = i & 31;
        float4 v = Y[i];
        float4 a = __ldg((const float4*)g_a2 + c4);
        float4 c = __ldg((const float4*)g_c2 + c4);
        v.x = fmaf(a.x, v.x, c.x);
        v.y = fmaf(a.y, v.y, c.y);
        v.z = fmaf(a.z, v.z, c.z);
        v.w = fmaf(a.w, v.w, c.w);
        Y[i] = v;
    }
}

// ---------------- launcher ----------------
extern "C" void kernel_launch(void* const* d_in, const int* in_sizes, int n_in,
                              void* d_out, int out_size) {
    const float* x   = (const float*)d_in[0];
    const void*  eix = d_in[1];
    const float* W1  = (const float*)d_in[2];
    const float* b1  = (const float*)d_in[3];
    const float* g1  = (const float*)d_in[4];
    const float* be1 = (const float*)d_in[5];
    const float* W2  = (const float*)d_in[6];
    const float* b2  = (const float*)d_in[7];
    const float* g2  = (const float*)d_in[8];
    const float* be2 = (const float*)d_in[9];
    float* out = (float*)d_out;

    const int N = in_sizes[0] / 64;
    const int E = in_sizes[1] / 2;

    const int SMEM1 = (128 * 64 + 64 * 128) * 4;     // 65 536 B
    const int SMEM2 = (128 * 128 + 128 * 128) * 4;   // 131 072 B
    cudaFuncSetAttribute(k_gemm_relu_stats<64>, cudaFuncAttributeMaxDynamicSharedMemorySize, SMEM1);
    cudaFuncSetAttribute(k_gemm_relu_stats<128>, cudaFuncAttributeMaxDynamicSharedMemorySize, SMEM2);

    void *p_h0, *p_h1, *p_W2f, *p_b2f, *p_s1, *p_q1, *p_s2, *p_q2;
    cudaGetSymbolAddress(&p_h0, g_h0);
    cudaGetSymbolAddress(&p_h1, g_h1);
    cudaGetSymbolAddress(&p_W2f, g_W2f);
    cudaGetSymbolAddress(&p_b2f, g_b2f);
    cudaGetSymbolAddress(&p_s1, g_sum1);
    cudaGetSymbolAddress(&p_q1, g_ss1);
    cudaGetSymbolAddress(&p_s2, g_sum2);
    cudaGetSymbolAddress(&p_q2, g_ss2);

    const int GB = 148 * 8;
    const int gb_gemm = (N + 127) / 128;
    const float invN = 1.0f / (float)N;

    k_zero_stats<<<1, 128>>>();
    k_detect<<<1, 256>>>((const int*)eix, E);
    k_copy<<<GB, 256>>>((const float4*)x, N * 16);
    k_scatter<<<GB * 2, 256>>>(eix, x, E);
    k_gemm_relu_stats<64><<<gb_gemm, 256, SMEM1>>>(
        (const float*)p_h0, W1, b1, (float*)p_h1, N, (float*)p_s1, (float*)p_q1);
    k_fold1<<<1, 128>>>(W2, b2, g1, be1, invN);
    k_gemm_relu_stats<128><<<gb_gemm, 256, SMEM2>>>(
        (const float*)p_h1, (const float*)p_W2f, (const float*)p_b2f, out, N,
        (float*)p_s2, (float*)p_q2);
    k_a2c2<<<1, 128>>>(g2, be2, invN);
    k_bn2<<<GB, 256>>>((float4*)out, N * 32);
}

// round 3
// speedup vs baseline: 2.7144x; 1.0781x over previous
#include <cuda_runtime.h>

// ---------------- static device scratch (no allocation allowed) ----------------
#define MAXN 100000
__device__ float g_h0[MAXN * 64];     // agg (zeroed, scatter adds; GEMM1 adds x)
__device__ float g_h1[MAXN * 128];    // relu(h0 @ W1 + b1)  (BN1 folded into W2)
__device__ float g_W2f[128 * 128];    // BN1-folded W2
__device__ float g_b2f[128];          // BN1-folded b2
__device__ float g_sum1[128], g_ss1[128];
__device__ float g_sum2[128], g_ss2[128];
__device__ float g_a2[128], g_c2[128];
__device__ int   g_is64;

#define BN_EPS 1e-5f

// packed f32x2 FMA (sm_103a; PTX-only, ptxas never auto-fuses)
#define FMA2(d, a, b, c) \
    asm("fma.rn.f32x2 %0, %1, %2, %3;" : "=l"(d) : "l"(a), "l"(b), "l"(c))
#define DUP_F32X2(d, f) \
    asm("mov.b64 %0, {%1, %1};" : "=l"(d) : "f"(f))
#define UNPACK_F32X2(lo, hi, p) \
    asm("mov.b64 {%0, %1}, %2;" : "=f"(lo), "=f"(hi) : "l"(p))

// ---------------- zero per-launch stats ----------------
__global__ void k_zero_stats() {
    int j = threadIdx.x;
    if (j < 128) {
        g_sum1[j] = 0.f; g_ss1[j] = 0.f;
        g_sum2[j] = 0.f; g_ss2[j] = 0.f;
    }
}

// ---------------- zero g_h0 ----------------
__global__ void k_zero_h0(int n4) {
    float4* d = (float4*)g_h0;
    int stride = gridDim.x * blockDim.x;
    float4 z = make_float4(0.f, 0.f, 0.f, 0.f);
    for (int i = blockIdx.x * blockDim.x + threadIdx.x; i < n4; i += stride)
        d[i] = z;
}

// ---------------- detect int64 vs int32 edge_index ----------------
__global__ void k_detect(const int* __restrict__ idx, int n_pairs) {
    __shared__ int nz;
    if (threadIdx.x == 0) nz = 0;
    __syncthreads();
    int lim = n_pairs < 1024 ? n_pairs : 1024;
    for (int i = threadIdx.x; i < lim; i += blockDim.x)
        if (idx[2 * i + 1] != 0) nz = 1;   // benign race
    __syncthreads();
    if (threadIdx.x == 0) g_is64 = (nz == 0) ? 1 : 0;
}

// ---------------- edge scatter: h0[dst] += x[src]  (vector RED, L2-resident) ----------------
__global__ void k_scatter(const void* __restrict__ eptr, const float* __restrict__ x, int E) {
    const int is64 = g_is64;
    const long long total = (long long)E * 16;   // 16 float4-chunks per edge
    const long long stride = (long long)gridDim.x * blockDim.x;
    for (long long i = (long long)blockIdx.x * blockDim.x + threadIdx.x; i < total; i += stride) {
        int e = (int)(i >> 4);
        int c = (int)(i & 15);
        int src, dst;
        if (is64) {
            const long long* p = (const long long*)eptr;
            src = (int)p[e];
            dst = (int)p[E + e];
        } else {
            const int* p = (const int*)eptr;
            src = p[e];
            dst = p[E + e];
        }
        float4 v = __ldg((const float4*)x + (long long)src * 16 + c);
        float* d = g_h0 + (long long)dst * 64 + c * 4;
        asm volatile("red.global.add.v4.f32 [%0], {%1,%2,%3,%4};"
                     :: "l"(d), "f"(v.x), "f"(v.y), "f"(v.z), "f"(v.w) : "memory");
    }
}

// ---------------- register-tiled GEMM + relu + fused BN stats ----------------
// Block 256 thr, tile 128x128 (8x8 per thread), FFMA2 accumulators.
// W stored in smem as [k][half][tx] float4 (conflict-free LDS.128: bank=tx*4).
// x loaded as float4 per 4 k (warp-broadcast). ~6 LDS wavefronts/warp/k vs
// 32 FFMA2 issues -> FMA-pipe-bound.
// If ADDX: stage X[row] + X2[row] (folds the x + agg add into staging).
template <int K, bool ADDX>
__global__ void __launch_bounds__(256, 1)
k_gemm_relu_stats(const float* __restrict__ X, const float* __restrict__ X2,
                  const float* __restrict__ W, const float* __restrict__ B,
                  float* __restrict__ Y, int N,
                  float* __restrict__ gsum, float* __restrict__ gss) {
    extern __shared__ float smem[];
    float* sx = smem;               // 128 * K
    float* sw = smem + 128 * K;     // K * 128, layout [(k*2+half)*16 + tx] float4
    __shared__ float ssum[128], sss[128];

    const int tid  = threadIdx.x;
    const int row0 = blockIdx.x * 128;

    // stage W into interleaved conflict-free layout
    for (int f = tid; f < K * 32; f += 256) {
        int k  = f >> 5;
        int c4 = f & 31;
        float4 v = __ldg((const float4*)W + f);
        ((float4*)sw)[(k * 2 + (c4 & 1)) * 16 + (c4 >> 1)] = v;
    }

    // stage X tile (128 rows x K floats), zero-pad OOB rows
    for (int f = tid; f < 128 * (K / 4); f += 256) {
        int r  = f / (K / 4);
        int c4 = f % (K / 4);
        int row = row0 + r;
        float4 v = make_float4(0.f, 0.f, 0.f, 0.f);
        if (row < N) {
            v = __ldg((const float4*)(X + (long long)row * K) + c4);
            if (ADDX) {
                float4 u = __ldg((const float4*)(X2 + (long long)row * K) + c4);
                v.x += u.x; v.y += u.y; v.z += u.z; v.w += u.w;
            }
        }
        ((float4*)(sx + r * K))[c4] = v;
    }
    if (tid < 128) { ssum[tid] = 0.f; sss[tid] = 0.f; }
    __syncthreads();

    const int tx = tid & 15;    // cols tx*8 .. tx*8+7
    const int ty = tid >> 4;    // rows ty*8 .. ty*8+7
    const float* xb = sx + ty * 8 * K;
    const ulonglong2* swv = (const ulonglong2*)sw;

    unsigned long long acc[8][4];
#pragma unroll
    for (int i = 0; i < 8; i++)
#pragma unroll
        for (int j = 0; j < 4; j++) acc[i][j] = 0ULL;

    for (int k0 = 0; k0 < K; k0 += 4) {
        float4 xv[8];
#pragma unroll
        for (int i = 0; i < 8; i++)
            xv[i] = *(const float4*)(xb + i * K + k0);
#pragma unroll
        for (int kk = 0; kk < 4; kk++) {
            ulonglong2 wa = swv[((k0 + kk) * 2 + 0) * 16 + tx];
            ulonglong2 wc = swv[((k0 + kk) * 2 + 1) * 16 + tx];
#pragma unroll
            for (int i = 0; i < 8; i++) {
                float xs = (kk == 0) ? xv[i].x : (kk == 1) ? xv[i].y
                         : (kk == 2) ? xv[i].z : xv[i].w;
                unsigned long long xp;
                DUP_F32X2(xp, xs);
                FMA2(acc[i][0], xp, wa.x, acc[i][0]);
                FMA2(acc[i][1], xp, wa.y, acc[i][1]);
                FMA2(acc[i][2], xp, wc.x, acc[i][2]);
                FMA2(acc[i][3], xp, wc.y, acc[i][3]);
            }
        }
    }

    // bias for my 8 cols
    float bias[8];
#pragma unroll
    for (int j = 0; j < 8; j++) bias[j] = __ldg(B + tx * 8 + j);

    float csum[8], csq[8];
#pragma unroll
    for (int j = 0; j < 8; j++) { csum[j] = 0.f; csq[j] = 0.f; }

#pragma unroll
    for (int i = 0; i < 8; i++) {
        int row = row0 + ty * 8 + i;
        if (row < N) {
            float o[8];
#pragma unroll
            for (int j = 0; j < 4; j++)
                UNPACK_F32X2(o[2 * j], o[2 * j + 1], acc[i][j]);
#pragma unroll
            for (int j = 0; j < 8; j++) {
                o[j] = fmaxf(o[j] + bias[j], 0.f);
                csum[j] += o[j];
                csq[j]  = fmaf(o[j], o[j], csq[j]);
            }
            float* yr = Y + (long long)row * 128 + tx * 8;
            ((float4*)yr)[0] = make_float4(o[0], o[1], o[2], o[3]);
            ((float4*)yr)[1] = make_float4(o[4], o[5], o[6], o[7]);
        }
    }

    // block-level stats reduction, then one global atomic per feature
#pragma unroll
    for (int j = 0; j < 8; j++) {
        atomicAdd(&ssum[tx * 8 + j], csum[j]);
        atomicAdd(&sss[tx * 8 + j], csq[j]);
    }
    __syncthreads();
    if (tid < 128) {
        atomicAdd(&gsum[tid], ssum[tid]);
        atomicAdd(&gss[tid], sss[tid]);
    }
}

// ---------------- fold BN1 into W2/b2: W2f = diag(a1) W2, b2f = b2 + c1^T W2 ----------------
__global__ void k_fold1(const float* __restrict__ W2, const float* __restrict__ b2,
                        const float* __restrict__ g1, const float* __restrict__ be1,
                        float invN) {
    __shared__ float a_s[128], c_s[128];
    int j = threadIdx.x;
    float mean = g_sum1[j] * invN;
    float var  = g_ss1[j] * invN - mean * mean;
    float a    = g1[j] * rsqrtf(var + BN_EPS);
    a_s[j] = a;
    c_s[j] = be1[j] - a * mean;
    __syncthreads();
    float acc = 0.f;
    for (int k = 0; k < 128; k++) {
        float w = W2[k * 128 + j];
        g_W2f[k * 128 + j] = a_s[k] * w;
        acc = fmaf(c_s[k], w, acc);
    }
    g_b2f[j] = b2[j] + acc;
}

// ---------------- BN2 coefficients ----------------
__global__ void k_a2c2(const float* __restrict__ g2, const float* __restrict__ be2, float invN) {
    int j = threadIdx.x;
    float mean = g_sum2[j] * invN;
    float var  = g_ss2[j] * invN - mean * mean;
    float a    = g2[j] * rsqrtf(var + BN_EPS);
    g_a2[j] = a;
    g_c2[j] = be2[j] - a * mean;
}

// ---------------- BN2 apply in place on d_out ----------------
__global__ void k_bn2(float4* __restrict__ Y, int n4) {
    int stride = gridDim.x * blockDim.x;
    for (int i = blockIdx.x * blockDim.x + threadIdx.x; i < n4; i += stride) {
        int c4 = i & 31;
        float4 v = Y[i];
        float4 a = __ldg((const float4*)g_a2 + c4);
        float4 c = __ldg((const float4*)g_c2 + c4);
        v.x = fmaf(a.x, v.x, c.x);
        v.y = fmaf(a.y, v.y, c.y);
        v.z = fmaf(a.z, v.z, c.z);
        v.w = fmaf(a.w, v.w, c.w);
        Y[i] = v;
    }
}

// ---------------- launcher ----------------
extern "C" void kernel_launch(void* const* d_in, const int* in_sizes, int n_in,
                              void* d_out, int out_size) {
    const float* x   = (const float*)d_in[0];
    const void*  eix = d_in[1];
    const float* W1  = (const float*)d_in[2];
    const float* b1  = (const float*)d_in[3];
    const float* g1  = (const float*)d_in[4];
    const float* be1 = (const float*)d_in[5];
    const float* W2  = (const float*)d_in[6];
    const float* b2  = (const float*)d_in[7];
    const float* g2  = (const float*)d_in[8];
    const float* be2 = (const float*)d_in[9];
    float* out = (float*)d_out;

    const int N = in_sizes[0] / 64;
    const int E = in_sizes[1] / 2;

    const int SMEM1 = (128 * 64 + 64 * 128) * 4;     // 65 536 B
    const int SMEM2 = (128 * 128 + 128 * 128) * 4;   // 131 072 B
    cudaFuncSetAttribute(k_gemm_relu_stats<64, true>,
                         cudaFuncAttributeMaxDynamicSharedMemorySize, SMEM1);
    cudaFuncSetAttribute(k_gemm_relu_stats<128, false>,
                         cudaFuncAttributeMaxDynamicSharedMemorySize, SMEM2);

    void *p_h0, *p_h1, *p_W2f, *p_b2f, *p_s1, *p_q1, *p_s2, *p_q2;
    cudaGetSymbolAddress(&p_h0, g_h0);
    cudaGetSymbolAddress(&p_h1, g_h1);
    cudaGetSymbolAddress(&p_W2f, g_W2f);
    cudaGetSymbolAddress(&p_b2f, g_b2f);
    cudaGetSymbolAddress(&p_s1, g_sum1);
    cudaGetSymbolAddress(&p_q1, g_ss1);
    cudaGetSymbolAddress(&p_s2, g_sum2);
    cudaGetSymbolAddress(&p_q2, g_ss2);

    const int GB = 148 * 8;
    const int gb_gemm = (N + 127) / 128;
    const float invN = 1.0f / (float)N;

    k_zero_stats<<<1, 128>>>();
    k_detect<<<1, 256>>>((const int*)eix, E);
    k_zero_h0<<<GB, 256>>>(N * 16);
    k_scatter<<<GB * 2, 256>>>(eix, x, E);
    k_gemm_relu_stats<64, true><<<gb_gemm, 256, SMEM1>>>(
        (const float*)p_h0, x, W1, b1, (float*)p_h1, N, (float*)p_s1, (float*)p_q1);
    k_fold1<<<1, 128>>>(W2, b2, g1, be1, invN);
    k_gemm_relu_stats<128, false><<<gb_gemm, 256, SMEM2>>>(
        (const float*)p_h1, nullptr, (const float*)p_W2f, (const float*)p_b2f, out, N,
        (float*)p_s2, (float*)p_q2);
    k_a2c2<<<1, 128>>>(g2, be2, invN);
    k_bn2<<<GB, 256>>>((float4*)out, N * 32);
}